// round 1
// baseline (speedup 1.0000x reference)
#include <cuda_runtime.h>

// Problem constants
#define HH 2048
#define WW 2048
#define PP (HH * WW)
#define NBINS 256

// Pass-1 tiling: each thread owns 4 consecutive columns and a strip of ROWS rows.
#define TPB1 128
#define ROWS 16
#define STRIPS (HH / ROWS)              // 128
#define GRID1X (WW / (TPB1 * 4))        // 4

// ---------------- device scratch (static allocation only) ----------------
__device__ double g_acc[6];      // 0:recon 1:Sum m 2:Sum dm 3:Sum L*e^-10Rg 4:Sum dL*e^-10|dRg| 5:eq
__device__ unsigned int g_hist[NBINS];
__device__ unsigned int g_minbits;
__device__ unsigned int g_maxbits;
__device__ float g_cdf[NBINS];
__device__ float g_immax[PP];
__device__ float g_rmax[PP];

// ---------------- init ----------------
__global__ void k_init() {
    int t = threadIdx.x;
    if (t < 6) g_acc[t] = 0.0;
    g_hist[t] = 0u;
    if (t == 0) { g_minbits = 0x7f800000u; g_maxbits = 0u; }
}

// PIL 'L' grayscale, integer-exact. Inputs are uniform [0,1) so clip is a no-op.
__device__ __forceinline__ int gray_i(float r, float g, float b) {
    int q0 = (int)(r * 255.0f);   // trunc == floor for non-negative
    int q1 = (int)(g * 255.0f);
    int q2 = (int)(b * 255.0f);
    return (q0 * 19595 + q1 * 38470 + q2 * 7471 + 32768) >> 16;
}

// ---------------- pass 1: fused elementwise + smoothness + min/max ----------------
__global__ void __launch_bounds__(TPB1) k_pass1(const float* __restrict__ im,
                                                const float* __restrict__ Rp,
                                                const float* __restrict__ Lp) {
    __shared__ float eLut[NBINS];
    for (int i = threadIdx.x; i < NBINS; i += TPB1)
        eLut[i] = expf(-10.0f * (float)i * (1.0f / 255.0f));
    __syncthreads();

    const int c4 = (blockIdx.x * TPB1 + threadIdx.x) * 4;
    const int r0 = blockIdx.y * ROWS;

    float sRecon = 0.f, sLexp = 0.f, sGLexp = 0.f;
    int   sM = 0, sDM = 0;
    float vmn = __int_as_float(0x7f800000), vmx = 0.f;

    int   pm[4];
    float pl[4];
#pragma unroll
    for (int j = 0; j < 4; j++) { pm[j] = 0; pl[j] = 0.f; }

    if (r0 > 0) {  // recompute previous row's gray + L for gradient continuity
        int idx = (r0 - 1) * WW + c4;
        float4 a = *(const float4*)(Rp + idx);
        float4 b = *(const float4*)(Rp + idx + PP);
        float4 c = *(const float4*)(Rp + idx + 2 * PP);
        float4 l = *(const float4*)(Lp + idx);
        const float *ap = &a.x, *bp = &b.x, *cp = &c.x, *lp = &l.x;
#pragma unroll
        for (int j = 0; j < 4; j++) { pm[j] = gray_i(ap[j], bp[j], cp[j]); pl[j] = lp[j]; }
    }

    int idx = r0 * WW + c4;
#pragma unroll 4
    for (int r = 0; r < ROWS; ++r, idx += WW) {
        float4 i0 = *(const float4*)(im + idx);
        float4 i1 = *(const float4*)(im + idx + PP);
        float4 i2 = *(const float4*)(im + idx + 2 * PP);
        float4 R0 = *(const float4*)(Rp + idx);
        float4 R1 = *(const float4*)(Rp + idx + PP);
        float4 R2 = *(const float4*)(Rp + idx + 2 * PP);
        float4 l4 = *(const float4*)(Lp + idx);
        const float *p0 = &i0.x, *p1 = &i1.x, *p2 = &i2.x;
        const float *q0 = &R0.x, *q1 = &R1.x, *q2 = &R2.x, *pl4 = &l4.x;
        float4 oim, orm;
        float *oimp = &oim.x, *ormp = &orm.x;
#pragma unroll
        for (int j = 0; j < 4; ++j) {
            float a0 = p0[j], a1 = p1[j], a2 = p2[j];
            float r0v = q0[j], r1v = q1[j], r2v = q2[j];
            float lv = pl4[j];
            float imx = fmaxf(a0, fmaxf(a1, a2));
            oimp[j] = imx;
            vmn = fminf(vmn, imx);
            vmx = fmaxf(vmx, imx);
            ormp[j] = fmaxf(r0v, fmaxf(r1v, r2v));
            sRecon += fabsf(fmaf(r0v, lv, -a0));
            sRecon += fabsf(fmaf(r1v, lv, -a1));
            sRecon += fabsf(fmaf(r2v, lv, -a2));
            int m = gray_i(r0v, r1v, r2v);
            sM += m;
            sLexp += fabsf(lv) * eLut[m];
            int dm = m - pm[j];
            dm = dm < 0 ? -dm : dm;
            sDM += dm;
            sGLexp += fabsf(lv - pl[j]) * eLut[dm];
            pm[j] = m;
            pl[j] = lv;
        }
        *(float4*)(g_immax + idx) = oim;
        *(float4*)(g_rmax + idx) = orm;
    }

    if (r0 + ROWS == HH) {  // trailing i=H term of the padded vertical difference
#pragma unroll
        for (int j = 0; j < 4; j++) {
            sDM += pm[j];
            sGLexp += fabsf(pl[j]) * eLut[pm[j]];
        }
    }

    // block reduction
    const unsigned FULL = 0xffffffffu;
    for (int o = 16; o; o >>= 1) {
        sRecon += __shfl_down_sync(FULL, sRecon, o);
        sLexp  += __shfl_down_sync(FULL, sLexp, o);
        sGLexp += __shfl_down_sync(FULL, sGLexp, o);
        sM     += __shfl_down_sync(FULL, sM, o);
        sDM    += __shfl_down_sync(FULL, sDM, o);
        vmn = fminf(vmn, __shfl_down_sync(FULL, vmn, o));
        vmx = fmaxf(vmx, __shfl_down_sync(FULL, vmx, o));
    }
    __shared__ float shf[3][4];
    __shared__ int   shi[2][4];
    __shared__ float shm[2][4];
    int lane = threadIdx.x & 31, wid = threadIdx.x >> 5;
    if (lane == 0) {
        shf[0][wid] = sRecon; shf[1][wid] = sLexp; shf[2][wid] = sGLexp;
        shi[0][wid] = sM;     shi[1][wid] = sDM;
        shm[0][wid] = vmn;    shm[1][wid] = vmx;
    }
    __syncthreads();
    if (threadIdx.x == 0) {
        float a = 0, b = 0, c = 0; int m0 = 0, m1 = 0;
        float mnv = shm[0][0], mxv = shm[1][0];
        for (int w = 0; w < 4; w++) {
            a += shf[0][w]; b += shf[1][w]; c += shf[2][w];
            m0 += shi[0][w]; m1 += shi[1][w];
            mnv = fminf(mnv, shm[0][w]); mxv = fmaxf(mxv, shm[1][w]);
        }
        atomicAdd(&g_acc[0], (double)a);
        atomicAdd(&g_acc[1], (double)m0);
        atomicAdd(&g_acc[2], (double)m1);
        atomicAdd(&g_acc[3], (double)b);
        atomicAdd(&g_acc[4], (double)c);
        atomicMin(&g_minbits, __float_as_uint(mnv));
        atomicMax(&g_maxbits, __float_as_uint(mxv));
    }
}

// ---------------- pass 2: histogram ----------------
__global__ void __launch_bounds__(256) k_hist() {
    __shared__ unsigned int sh[NBINS];
    sh[threadIdx.x] = 0u;
    __syncthreads();
    const float mn = __uint_as_float(g_minbits);
    const float mx = __uint_as_float(g_maxbits);
    const float scale = 256.0f / (mx - mn);
    const int stride = gridDim.x * blockDim.x * 4;
    for (int i = (blockIdx.x * blockDim.x + threadIdx.x) * 4; i < PP; i += stride) {
        float4 x4 = *(const float4*)(g_immax + i);
        const float* xp = &x4.x;
#pragma unroll
        for (int j = 0; j < 4; j++) {
            int k = (int)((xp[j] - mn) * scale);
            k = k > 255 ? 255 : k;
            atomicAdd(&sh[k], 1u);
        }
    }
    __syncthreads();
    atomicAdd(&g_hist[threadIdx.x], sh[threadIdx.x]);
}

// ---------------- pass 3: cdf (cumcounts / N — density & width cancel) ----------------
__global__ void k_cdf() {
    double cum = 0.0;
    for (int k = 0; k < NBINS; k++) {
        cum += (double)g_hist[k];
        g_cdf[k] = (float)(cum * (1.0 / (double)PP));
    }
}

// ---------------- pass 4: interp(im_max) -> im_eq, accumulate |R_max - im_eq| ----------------
__global__ void __launch_bounds__(256) k_pass4() {
    __shared__ float cdf[NBINS];
    cdf[threadIdx.x] = g_cdf[threadIdx.x];
    __syncthreads();
    const float mn = __uint_as_float(g_minbits);
    const float mx = __uint_as_float(g_maxbits);
    const float scale = 256.0f / (mx - mn);
    float s = 0.f;
    const int stride = gridDim.x * blockDim.x * 4;
    for (int i = (blockIdx.x * blockDim.x + threadIdx.x) * 4; i < PP; i += stride) {
        float4 x4 = *(const float4*)(g_immax + i);
        float4 r4 = *(const float4*)(g_rmax + i);
        const float *xp = &x4.x, *rp = &r4.x;
#pragma unroll
        for (int j = 0; j < 4; j++) {
            float u = (xp[j] - mn) * scale;
            int k = (int)u;
            float eq;
            if (k >= 255) {
                eq = cdf[255];
            } else {
                float c0 = cdf[k];
                eq = c0 + (u - (float)k) * (cdf[k + 1] - c0);
            }
            s += fabsf(rp[j] - eq);
        }
    }
    const unsigned FULL = 0xffffffffu;
    for (int o = 16; o; o >>= 1) s += __shfl_down_sync(FULL, s, o);
    __shared__ float sh[8];
    int lane = threadIdx.x & 31, wid = threadIdx.x >> 5;
    if (lane == 0) sh[wid] = s;
    __syncthreads();
    if (threadIdx.x == 0) {
        float t = 0.f;
        for (int w = 0; w < (int)(blockDim.x >> 5); w++) t += sh[w];
        atomicAdd(&g_acc[5], (double)t);
    }
}

// ---------------- pass 5: combine ----------------
__global__ void k_final(float* out) {
    double recon = g_acc[0] / (3.0 * (double)PP);
    double eq    = g_acc[5] / (double)PP;
    double D     = 2.0 * (double)(HH + 1) * (double)(WW + 2);
    double rs    = ((g_acc[2] + 2.0 * g_acc[1]) * (1.0 / 255.0)) / D;
    double ism   = (g_acc[4] + 2.0 * g_acc[3]) / D;
    out[0] = (float)(recon + 0.1 * ism + 0.1 * eq + 0.01 * rs);
}

// ---------------- launch ----------------
extern "C" void kernel_launch(void* const* d_in, const int* in_sizes, int n_in,
                              void* d_out, int out_size) {
    // Identify inputs by size: two of 3*H*W (input_im first, then R) and one of H*W (L).
    const float* im = nullptr;
    const float* Rp = nullptr;
    const float* Lp = nullptr;
    for (int i = 0; i < n_in; i++) {
        if (in_sizes[i] == PP) {
            Lp = (const float*)d_in[i];
        } else if (!im) {
            im = (const float*)d_in[i];
        } else {
            Rp = (const float*)d_in[i];
        }
    }

    k_init<<<1, 256>>>();
    dim3 g1(GRID1X, STRIPS);
    k_pass1<<<g1, TPB1>>>(im, Rp, Lp);
    k_hist<<<256, 256>>>();
    k_cdf<<<1, 1>>>();
    k_pass4<<<512, 256>>>();
    k_final<<<1, 1>>>((float*)d_out);
}

// round 3
// speedup vs baseline: 1.8645x; 1.8645x over previous
#include <cuda_runtime.h>

// Problem constants
#define HH 2048
#define WW 2048
#define PP (HH * WW)
#define NBINS 256

// Pass-1 tiling: each thread owns 4 consecutive columns and a strip of ROWS rows.
#define TPB1 128
#define ROWS 16
#define STRIPS (HH / ROWS)              // 128
#define GRID1X (WW / (TPB1 * 4))        // 4

// ---------------- device scratch (static allocation only) ----------------
__device__ double g_acc[6];      // 0:recon 1:Sum m 2:Sum dm 3:Sum L*e^-10Rg 4:Sum dL*e^-10|dRg| 5:eq
__device__ unsigned int g_hist[NBINS];
__device__ unsigned int g_minbits;
__device__ unsigned int g_maxbits;
__device__ float g_cdf[NBINS];
__device__ float g_immax[PP];
__device__ float g_rmax[PP];

// ---------------- init ----------------
__global__ void k_init() {
    int t = threadIdx.x;
    if (t < 6) g_acc[t] = 0.0;
    g_hist[t] = 0u;
    if (t == 0) { g_minbits = 0x7f800000u; g_maxbits = 0u; }
}

// PIL 'L' grayscale, integer-exact. Inputs are uniform [0,1) so clip is a no-op.
__device__ __forceinline__ int gray_i(float r, float g, float b) {
    int q0 = (int)(r * 255.0f);   // trunc == floor for non-negative
    int q1 = (int)(g * 255.0f);
    int q2 = (int)(b * 255.0f);
    return (q0 * 19595 + q1 * 38470 + q2 * 7471 + 32768) >> 16;
}

// ---------------- pass 1: fused elementwise + smoothness + min/max ----------------
__global__ void __launch_bounds__(TPB1) k_pass1(const float* __restrict__ im,
                                                const float* __restrict__ Rp,
                                                const float* __restrict__ Lp) {
    __shared__ float eLut[NBINS];
    for (int i = threadIdx.x; i < NBINS; i += TPB1)
        eLut[i] = expf(-10.0f * (float)i * (1.0f / 255.0f));
    __syncthreads();

    const int c4 = (blockIdx.x * TPB1 + threadIdx.x) * 4;
    const int r0 = blockIdx.y * ROWS;

    float sRecon = 0.f, sLexp = 0.f, sGLexp = 0.f;
    int   sM = 0, sDM = 0;
    float vmn = __int_as_float(0x7f800000), vmx = 0.f;

    int   pm[4];
    float pl[4];
#pragma unroll
    for (int j = 0; j < 4; j++) { pm[j] = 0; pl[j] = 0.f; }

    if (r0 > 0) {  // recompute previous row's gray + L for gradient continuity
        int idx = (r0 - 1) * WW + c4;
        float4 a = *(const float4*)(Rp + idx);
        float4 b = *(const float4*)(Rp + idx + PP);
        float4 c = *(const float4*)(Rp + idx + 2 * PP);
        float4 l = *(const float4*)(Lp + idx);
        const float *ap = &a.x, *bp = &b.x, *cp = &c.x, *lp = &l.x;
#pragma unroll
        for (int j = 0; j < 4; j++) { pm[j] = gray_i(ap[j], bp[j], cp[j]); pl[j] = lp[j]; }
    }

    int idx = r0 * WW + c4;
#pragma unroll 4
    for (int r = 0; r < ROWS; ++r, idx += WW) {
        float4 i0 = *(const float4*)(im + idx);
        float4 i1 = *(const float4*)(im + idx + PP);
        float4 i2 = *(const float4*)(im + idx + 2 * PP);
        float4 R0 = *(const float4*)(Rp + idx);
        float4 R1 = *(const float4*)(Rp + idx + PP);
        float4 R2 = *(const float4*)(Rp + idx + 2 * PP);
        float4 l4 = *(const float4*)(Lp + idx);
        const float *p0 = &i0.x, *p1 = &i1.x, *p2 = &i2.x;
        const float *q0 = &R0.x, *q1 = &R1.x, *q2 = &R2.x, *pl4 = &l4.x;
        float4 oim, orm;
        float *oimp = &oim.x, *ormp = &orm.x;
#pragma unroll
        for (int j = 0; j < 4; ++j) {
            float a0 = p0[j], a1 = p1[j], a2 = p2[j];
            float r0v = q0[j], r1v = q1[j], r2v = q2[j];
            float lv = pl4[j];
            float imx = fmaxf(a0, fmaxf(a1, a2));
            oimp[j] = imx;
            vmn = fminf(vmn, imx);
            vmx = fmaxf(vmx, imx);
            ormp[j] = fmaxf(r0v, fmaxf(r1v, r2v));
            sRecon += fabsf(fmaf(r0v, lv, -a0));
            sRecon += fabsf(fmaf(r1v, lv, -a1));
            sRecon += fabsf(fmaf(r2v, lv, -a2));
            int m = gray_i(r0v, r1v, r2v);
            sM += m;
            sLexp += fabsf(lv) * eLut[m];
            int dm = m - pm[j];
            dm = dm < 0 ? -dm : dm;
            sDM += dm;
            sGLexp += fabsf(lv - pl[j]) * eLut[dm];
            pm[j] = m;
            pl[j] = lv;
        }
        *(float4*)(g_immax + idx) = oim;
        *(float4*)(g_rmax + idx) = orm;
    }

    if (r0 + ROWS == HH) {  // trailing i=H term of the padded vertical difference
#pragma unroll
        for (int j = 0; j < 4; j++) {
            sDM += pm[j];
            sGLexp += fabsf(pl[j]) * eLut[pm[j]];
        }
    }

    // block reduction
    const unsigned FULL = 0xffffffffu;
    for (int o = 16; o; o >>= 1) {
        sRecon += __shfl_down_sync(FULL, sRecon, o);
        sLexp  += __shfl_down_sync(FULL, sLexp, o);
        sGLexp += __shfl_down_sync(FULL, sGLexp, o);
        sM     += __shfl_down_sync(FULL, sM, o);
        sDM    += __shfl_down_sync(FULL, sDM, o);
        vmn = fminf(vmn, __shfl_down_sync(FULL, vmn, o));
        vmx = fmaxf(vmx, __shfl_down_sync(FULL, vmx, o));
    }
    __shared__ float shf[3][4];
    __shared__ int   shi[2][4];
    __shared__ float shm[2][4];
    int lane = threadIdx.x & 31, wid = threadIdx.x >> 5;
    if (lane == 0) {
        shf[0][wid] = sRecon; shf[1][wid] = sLexp; shf[2][wid] = sGLexp;
        shi[0][wid] = sM;     shi[1][wid] = sDM;
        shm[0][wid] = vmn;    shm[1][wid] = vmx;
    }
    __syncthreads();
    if (threadIdx.x == 0) {
        float a = 0, b = 0, c = 0; int m0 = 0, m1 = 0;
        float mnv = shm[0][0], mxv = shm[1][0];
        for (int w = 0; w < 4; w++) {
            a += shf[0][w]; b += shf[1][w]; c += shf[2][w];
            m0 += shi[0][w]; m1 += shi[1][w];
            mnv = fminf(mnv, shm[0][w]); mxv = fmaxf(mxv, shm[1][w]);
        }
        atomicAdd(&g_acc[0], (double)a);
        atomicAdd(&g_acc[1], (double)m0);
        atomicAdd(&g_acc[2], (double)m1);
        atomicAdd(&g_acc[3], (double)b);
        atomicAdd(&g_acc[4], (double)c);
        atomicMin(&g_minbits, __float_as_uint(mnv));
        atomicMax(&g_maxbits, __float_as_uint(mxv));
    }
}

// ---------------- pass 2: histogram ----------------
__global__ void __launch_bounds__(256) k_hist() {
    __shared__ unsigned int sh[NBINS];
    sh[threadIdx.x] = 0u;
    __syncthreads();
    const float mn = __uint_as_float(g_minbits);
    const float mx = __uint_as_float(g_maxbits);
    const float scale = 256.0f / (mx - mn);
    const int stride = gridDim.x * blockDim.x * 4;
    for (int i = (blockIdx.x * blockDim.x + threadIdx.x) * 4; i < PP; i += stride) {
        float4 x4 = *(const float4*)(g_immax + i);
        const float* xp = &x4.x;
#pragma unroll
        for (int j = 0; j < 4; j++) {
            int k = (int)((xp[j] - mn) * scale);
            k = k > 255 ? 255 : k;
            atomicAdd(&sh[k], 1u);
        }
    }
    __syncthreads();
    atomicAdd(&g_hist[threadIdx.x], sh[threadIdx.x]);
}

// ---------------- pass 3: parallel CDF scan (exact integer prefix sum) ----------------
// Cumulative counts <= 2^22, integers — exact. cdf[k] = cum[k] / PP.
__global__ void __launch_bounds__(NBINS) k_cdf() {
    const int t = threadIdx.x;
    unsigned int v = g_hist[t];

    // intra-warp inclusive scan
    const unsigned FULL = 0xffffffffu;
#pragma unroll
    for (int o = 1; o < 32; o <<= 1) {
        unsigned int n = __shfl_up_sync(FULL, v, o);
        if ((t & 31) >= o) v += n;
    }

    // cross-warp offsets
    __shared__ unsigned int wsum[8];
    int lane = t & 31, wid = t >> 5;
    if (lane == 31) wsum[wid] = v;
    __syncthreads();
    if (wid == 0) {
        unsigned int w = (lane < 8) ? wsum[lane] : 0u;
#pragma unroll
        for (int o = 1; o < 8; o <<= 1) {
            unsigned int n = __shfl_up_sync(FULL, w, o);
            if (lane >= o) w += n;
        }
        if (lane < 8) wsum[lane] = w;
    }
    __syncthreads();
    if (wid > 0) v += wsum[wid - 1];

    g_cdf[t] = (float)v * (1.0f / (float)PP);
}

// ---------------- pass 4: interp(im_max) -> im_eq, accumulate |R_max - im_eq| ----------------
__global__ void __launch_bounds__(256) k_pass4() {
    __shared__ float cdf[NBINS];
    cdf[threadIdx.x] = g_cdf[threadIdx.x];
    __syncthreads();
    const float mn = __uint_as_float(g_minbits);
    const float mx = __uint_as_float(g_maxbits);
    const float scale = 256.0f / (mx - mn);
    float s = 0.f;
    const int stride = gridDim.x * blockDim.x * 4;
    for (int i = (blockIdx.x * blockDim.x + threadIdx.x) * 4; i < PP; i += stride) {
        float4 x4 = *(const float4*)(g_immax + i);
        float4 r4 = *(const float4*)(g_rmax + i);
        const float *xp = &x4.x, *rp = &r4.x;
#pragma unroll
        for (int j = 0; j < 4; j++) {
            float u = (xp[j] - mn) * scale;
            int k = (int)u;
            float eq;
            if (k >= 255) {
                eq = cdf[255];
            } else {
                float c0 = cdf[k];
                eq = c0 + (u - (float)k) * (cdf[k + 1] - c0);
            }
            s += fabsf(rp[j] - eq);
        }
    }
    const unsigned FULL = 0xffffffffu;
    for (int o = 16; o; o >>= 1) s += __shfl_down_sync(FULL, s, o);
    __shared__ float sh[8];
    int lane = threadIdx.x & 31, wid = threadIdx.x >> 5;
    if (lane == 0) sh[wid] = s;
    __syncthreads();
    if (threadIdx.x == 0) {
        float t = 0.f;
        for (int w = 0; w < (int)(blockDim.x >> 5); w++) t += sh[w];
        atomicAdd(&g_acc[5], (double)t);
    }
}

// ---------------- pass 5: combine ----------------
__global__ void k_final(float* out) {
    double recon = g_acc[0] / (3.0 * (double)PP);
    double eq    = g_acc[5] / (double)PP;
    double D     = 2.0 * (double)(HH + 1) * (double)(WW + 2);
    double rs    = ((g_acc[2] + 2.0 * g_acc[1]) * (1.0 / 255.0)) / D;
    double ism   = (g_acc[4] + 2.0 * g_acc[3]) / D;
    out[0] = (float)(recon + 0.1 * ism + 0.1 * eq + 0.01 * rs);
}

// ---------------- launch ----------------
extern "C" void kernel_launch(void* const* d_in, const int* in_sizes, int n_in,
                              void* d_out, int out_size) {
    // Identify inputs by size: two of 3*H*W (input_im first, then R) and one of H*W (L).
    const float* im = nullptr;
    const float* Rp = nullptr;
    const float* Lp = nullptr;
    for (int i = 0; i < n_in; i++) {
        if (in_sizes[i] == PP) {
            Lp = (const float*)d_in[i];
        } else if (!im) {
            im = (const float*)d_in[i];
        } else {
            Rp = (const float*)d_in[i];
        }
    }

    k_init<<<1, 256>>>();
    dim3 g1(GRID1X, STRIPS);
    k_pass1<<<g1, TPB1>>>(im, Rp, Lp);
    k_hist<<<256, 256>>>();
    k_cdf<<<1, NBINS>>>();
    k_pass4<<<512, 256>>>();
    k_final<<<1, 1>>>((float*)d_out);
}